// round 7
// baseline (speedup 1.0000x reference)
#include <cuda_runtime.h>
#include <cuda_bf16.h>
#include <cstdint>

// ============================================================================
// T=1, h0=c0=0 => w_hh* unused, f-gate unused. Chain of small GEMMs on HMMA
// (mma.sync m16n8k16 bf16; tcgen05 blocked by compute_103 virtual arch).
// bf16x3: A segs [hi,hi,lo] vs W segs [Whi,Wlo,Whi].
// R7: 384 threads (12 warps) -> 170-reg budget, kills the spills that pinned
// R5/R6 at regs=128. Single-buffer accumulators (R5 structure), A hi+lo fully
// in registers per layer, fused activation (R6: 6 MUFU/h, pre-scaled biases).
// Persistent: 148 CTAs; warp owns 32 rows, warp-private A smem buffer.
// ============================================================================

#define NT    384
#define GRID  148
#define AP    272
#define WIMG  84096
#define WARP_ABUF (32 * AP)
#define SMEM_BYTES (WIMG + 12 * WARP_ABUF)

#define WB_L0 0
#define WB_L1 24576
#define WB_L2 36864
#define WB_L3 49152
#define WB_L4 61440
#define WB_FC 73728
#define BIAS_OFF 81920

#define LOG2E  1.4426950408889634f
#define LOG2E2 2.8853901617765427f

__device__ __align__(16) unsigned char g_img[WIMG];

// ---------------- fast math ----------------
__device__ __forceinline__ float ex2f(float x) {
    float y; asm("ex2.approx.f32 %0, %1;" : "=f"(y) : "f"(x)); return y;
}
__device__ __forceinline__ float rcpf(float x) {
    float y; asm("rcp.approx.f32 %0, %1;" : "=f"(y) : "f"(x)); return y;
}
__device__ __forceinline__ uint32_t packbf2(float a, float b) {
    __nv_bfloat16 ha = __float2bfloat16_rn(a), hb = __float2bfloat16_rn(b);
    return (uint32_t)__bfloat16_as_ushort(ha) |
           ((uint32_t)__bfloat16_as_ushort(hb) << 16);
}
__device__ __forceinline__ float bflo(float v) {
    return v - __bfloat162float(__float2bfloat16_rn(v));
}

// fused LSTM activation: h = sig(o)*tanh(sig(i)*tanh(g)).
// biases arrive pre-scaled: bik = bI*log2e, bgk = bG*2*log2e, bok = bO*log2e.
__device__ __forceinline__ float act_h(float ci, float cg, float co,
                                       float bik, float bgk, float bok) {
    float A  = ex2f(fmaf(ci, LOG2E,  bik));      // e^i
    float Bv = ex2f(fmaf(cg, LOG2E2, bgk));      // e^{2g}
    float r1 = rcpf((A + 1.f) * (Bv + 1.f));
    float c2k = (A * (Bv - 1.f)) * LOG2E2 * r1;  // 2*log2e * sig(i)tanh(g)
    float Cc = ex2f(fmaf(co, LOG2E,  bok));      // e^o
    float D  = ex2f(c2k);                        // e^{2c}
    return (Cc * (D - 1.f)) * rcpf((Cc + 1.f) * (D + 1.f));
}

// ---------------- mma ----------------
__device__ __forceinline__ void mma_bf16(float c[4],
    const uint32_t a[4], uint32_t b0, uint32_t b1) {
    asm volatile(
        "mma.sync.aligned.m16n8k16.row.col.f32.bf16.bf16.f32 "
        "{%0,%1,%2,%3},{%4,%5,%6,%7},{%8,%9},{%0,%1,%2,%3};"
        : "+f"(c[0]), "+f"(c[1]), "+f"(c[2]), "+f"(c[3])
        : "r"(a[0]), "r"(a[1]), "r"(a[2]), "r"(a[3]), "r"(b0), "r"(b1));
}

// ---------------- weight pack (R4 layout; biases pre-scaled) ----------
__global__ void _LSTM_pack(const float* __restrict__ w_ih0,
                           const float* __restrict__ w_ih_rest,
                           const float* __restrict__ b_ih,
                           const float* __restrict__ b_hh,
                           const float* __restrict__ fc_w,
                           const float* __restrict__ fc_b) {
    int i = blockIdx.x * blockDim.x + threadIdx.x;
    if (i < 40960) {
        int fid = i >> 7, r = i & 127;
        int lane = r >> 2, reg = (r >> 1) & 1, half = r & 1;
        int n = lane >> 2;
        int kel = (lane & 3) * 2 + half + reg * 8;
        int layer, kh, ntn, fl;
        if (fid < 96)       { layer = 0; kh = 4; ntn = 12; fl = fid; }
        else if (fid < 288) { layer = 1 + (fid - 96) / 48; kh = 2; ntn = 12;
                              fl = (fid - 96) % 48; }
        else                { layer = 5; kh = 2; ntn = 8; fl = fid - 288; }
        int kidx = fl / ntn, nt = fl % ntn;
        int is_lo = kidx >= kh;
        int k = (is_lo ? kidx - kh : kidx) * 16 + kel;
        int j = nt * 8 + n;
        float w;
        if (layer == 0)      { int rr = j < 32 ? j : j + 32; w = w_ih0[rr * 64 + k]; }
        else if (layer < 5)  { int rr = j < 32 ? j : j + 32;
                               w = w_ih_rest[(layer - 1) * 4096 + rr * 32 + k]; }
        else                 w = fc_w[j * 32 + k];
        __nv_bfloat16 hi = __float2bfloat16_rn(w);
        __nv_bfloat16 v = is_lo ?
            __float2bfloat16_rn(w - __bfloat162float(hi)) : hi;
        *(__nv_bfloat16*)(g_img + fid * 256 + lane * 8 + reg * 4 + half * 2) = v;
    } else if (i < 40960 + 544) {
        int b = i - 40960; float v;
        if (b < 480) {
            int l = b / 96, j = b % 96;
            int rr = j < 32 ? j : j + 32;
            v = b_ih[l * 128 + rr] + b_hh[l * 128 + rr];
            v *= (j >= 32 && j < 64) ? LOG2E2 : LOG2E;   // g rows: 2*log2e
        } else v = fc_b[b - 480];
        *(float*)(g_img + BIAS_OFF + b * 4) = v;
    }
}

// -------- load A fragments (hi+lo) for the layer into registers --------
template<int KH>
__device__ __forceinline__ void load_A(
    const unsigned char* __restrict__ Abuf, int lane, int hiKB,
    uint32_t Ah[2][KH][4], uint32_t Al[2][KH][4])
{
    const int g = lane >> 2, q4 = lane & 3;
#pragma unroll
    for (int m = 0; m < 2; m++)
#pragma unroll
        for (int tk = 0; tk < KH; tk++) {
            const unsigned char* ab = Abuf + (m * 16 + g) * AP + 32 * tk + 4 * q4;
            Ah[m][tk][0] = *(const uint32_t*)ab;
            Ah[m][tk][1] = *(const uint32_t*)(ab + 8 * AP);
            Ah[m][tk][2] = *(const uint32_t*)(ab + 16);
            Ah[m][tk][3] = *(const uint32_t*)(ab + 8 * AP + 16);
            const unsigned char* al = ab + hiKB;
            Al[m][tk][0] = *(const uint32_t*)al;
            Al[m][tk][1] = *(const uint32_t*)(al + 8 * AP);
            Al[m][tk][2] = *(const uint32_t*)(al + 16);
            Al[m][tk][3] = *(const uint32_t*)(al + 8 * AP + 16);
        }
    __syncwarp();   // all lanes' A in regs before any h writes below
}

// -------- one LSTM layer: A in regs, i/g/o fused per 8-col n-group --------
template<int KH>
__device__ __forceinline__ void lstm_layer_reg(
    const unsigned char* __restrict__ wimg, uint32_t wbase,
    const float* __restrict__ biasK, unsigned char* __restrict__ Abuf,
    int lane, int hiKB)
{
    const int g = lane >> 2, q4 = lane & 3;
    uint32_t Ah[2][KH][4], Al[2][KH][4];
    load_A<KH>(Abuf, lane, hiKB, Ah, Al);

    const unsigned char* wp = wimg + wbase + lane * 8;

#pragma unroll
    for (int ntj = 0; ntj < 4; ntj++) {
        float Ci[2][4], Cg[2][4], Co[2][4];
#pragma unroll
        for (int m = 0; m < 2; m++)
#pragma unroll
            for (int q = 0; q < 4; q++) {
                Ci[m][q] = 0.f; Cg[m][q] = 0.f; Co[m][q] = 0.f;
            }
#pragma unroll
        for (int t = 0; t < 3 * KH; t++) {
            const int seg = t / KH, tk = t % KH;
            const int kg = (seg == 1) ? KH + tk : tk;
            const uint32_t* bi = (const uint32_t*)(wp + (uint32_t)(kg * 12 + ntj) * 256);
            const uint32_t* bg = (const uint32_t*)(wp + (uint32_t)(kg * 12 + 4 + ntj) * 256);
            const uint32_t* bo = (const uint32_t*)(wp + (uint32_t)(kg * 12 + 8 + ntj) * 256);
            uint32_t i0 = bi[0], i1 = bi[1];
            uint32_t g0 = bg[0], g1 = bg[1];
            uint32_t o0 = bo[0], o1 = bo[1];
#pragma unroll
            for (int m = 0; m < 2; m++) {
                const uint32_t* A = (seg == 2) ? Al[m][tk] : Ah[m][tk];
                mma_bf16(Ci[m], A, i0, i1);
                mma_bf16(Cg[m], A, g0, g1);
                mma_bf16(Co[m], A, o0, o1);
            }
        }
        const int col = ntj * 8 + q4 * 2;
        const float bi0 = biasK[col],      bi1 = biasK[col + 1];
        const float bg0 = biasK[32 + col], bg1 = biasK[33 + col];
        const float bo0 = biasK[64 + col], bo1 = biasK[65 + col];
#pragma unroll
        for (int m = 0; m < 2; m++) {
            float h0 = act_h(Ci[m][0], Cg[m][0], Co[m][0], bi0, bg0, bo0);
            float h1 = act_h(Ci[m][1], Cg[m][1], Co[m][1], bi1, bg1, bo1);
            float h2 = act_h(Ci[m][2], Cg[m][2], Co[m][2], bi0, bg0, bo0);
            float h3 = act_h(Ci[m][3], Cg[m][3], Co[m][3], bi1, bg1, bo1);
            unsigned char* r0 = Abuf + (m * 16 + g) * AP + 4 * (ntj * 4 + q4);
            unsigned char* r1 = r0 + 8 * AP;
            *(uint32_t*)r0        = packbf2(h0, h1);
            *(uint32_t*)(r0 + 64) = packbf2(bflo(h0), bflo(h1));
            *(uint32_t*)r1        = packbf2(h2, h3);
            *(uint32_t*)(r1 + 64) = packbf2(bflo(h2), bflo(h3));
        }
    }
    __syncwarp();
}

// -------- fc: 8 n-groups, A in regs, f32 outputs staged to Abuf --------
__device__ __forceinline__ void fc_reg(
    const unsigned char* __restrict__ wimg,
    const float* __restrict__ fb, unsigned char* __restrict__ Abuf, int lane)
{
    const int g = lane >> 2, q4 = lane & 3;
    uint32_t Ah[2][2][4], Al[2][2][4];
    load_A<2>(Abuf, lane, 64, Ah, Al);

    const unsigned char* wp = wimg + WB_FC + lane * 8;

#pragma unroll
    for (int ntj = 0; ntj < 8; ntj++) {
        float C[2][4];
#pragma unroll
        for (int m = 0; m < 2; m++)
#pragma unroll
            for (int q = 0; q < 4; q++) C[m][q] = 0.f;
#pragma unroll
        for (int t = 0; t < 6; t++) {
            const int seg = t / 2, tk = t % 2;
            const int kg = (seg == 1) ? 2 + tk : tk;
            const uint32_t* bf = (const uint32_t*)(wp + (uint32_t)(kg * 8 + ntj) * 256);
            uint32_t b0 = bf[0], b1 = bf[1];
#pragma unroll
            for (int m = 0; m < 2; m++) {
                const uint32_t* A = (seg == 2) ? Al[m][tk] : Ah[m][tk];
                mma_bf16(C[m], A, b0, b1);
            }
        }
        const int col = ntj * 8 + q4 * 2;
        const float b0 = fb[col], b1 = fb[col + 1];
#pragma unroll
        for (int m = 0; m < 2; m++) {
            float* r0 = (float*)(Abuf + (m * 16 + g) * AP + 4 * col);
            float* r1 = (float*)((unsigned char*)r0 + 8 * AP);
            r0[0] = C[m][0] + b0; r0[1] = C[m][1] + b1;
            r1[0] = C[m][2] + b0; r1[1] = C[m][3] + b1;
        }
    }
    __syncwarp();
}

// ---------------- main persistent kernel ----------------
__global__ void __launch_bounds__(NT, 1)
_LSTM_main(const float* __restrict__ x, float* __restrict__ out, int B) {
    extern __shared__ unsigned char smem[];
    const int tid = threadIdx.x;
    const int wid = tid >> 5;
    const int lane = tid & 31;

    // copy fragment image + biases to smem once
#pragma unroll 4
    for (int p = tid; p < WIMG / 16; p += NT)
        ((uint4*)smem)[p] = ((const uint4*)g_img)[p];
    __syncthreads();

    unsigned char* Abuf = smem + WIMG + wid * WARP_ABUF;
    const float* biasK = (const float*)(smem + BIAS_OFF);
    const float4* x4 = (const float4*)x;
    float4* o4 = (float4*)out;

    const int npair = (B + NT - 1) / NT;   // 384 rows per iter per CTA

#pragma unroll 1
    for (int it = blockIdx.x; it < npair; it += GRID) {
        const long long rowbase = (long long)it * NT + wid * 32;

        // ---- load 32 x-rows, convert to bf16 hi/lo, warp-private stage ----
#pragma unroll
        for (int i = 0; i < 16; i++) {
            int p = lane + i * 32;
            int r = p >> 4, c4 = p & 15;
            long long grow = rowbase + r;
            float4 v = (grow < B) ? x4[grow * 16 + c4]
                                  : make_float4(0.f, 0.f, 0.f, 0.f);
            uint32_t hi0 = packbf2(v.x, v.y), hi1 = packbf2(v.z, v.w);
            uint32_t lo0 = packbf2(bflo(v.x), bflo(v.y));
            uint32_t lo1 = packbf2(bflo(v.z), bflo(v.w));
            unsigned char* dst = Abuf + r * AP + 8 * c4;
            *(uint2*)dst         = make_uint2(hi0, hi1);
            *(uint2*)(dst + 128) = make_uint2(lo0, lo1);
        }
        __syncwarp();

        // ---- 5 LSTM layers + fc (in-place h: A is in regs) ----
        lstm_layer_reg<4>(smem, WB_L0, biasK,       Abuf, lane, 128);
        lstm_layer_reg<2>(smem, WB_L1, biasK + 96,  Abuf, lane, 64);
        lstm_layer_reg<2>(smem, WB_L2, biasK + 192, Abuf, lane, 64);
        lstm_layer_reg<2>(smem, WB_L3, biasK + 288, Abuf, lane, 64);
        lstm_layer_reg<2>(smem, WB_L4, biasK + 384, Abuf, lane, 64);
        fc_reg(smem, biasK + 480, Abuf, lane);

        // ---- coalesced f32 store ----
#pragma unroll
        for (int i = 0; i < 16; i++) {
            int p = lane + i * 32;
            int r = p >> 4, c4 = p & 15;
            long long grow = rowbase + r;
            if (grow < B)
                o4[grow * 16 + c4] = *(const float4*)(Abuf + r * AP + 16 * c4);
        }
        __syncwarp();
    }
}

// ---------------- launch ----------------
extern "C" void kernel_launch(void* const* d_in, const int* in_sizes, int n_in,
                              void* d_out, int out_size) {
    (void)n_in; (void)out_size;
    const float* x         = (const float*)d_in[0];
    const float* w_ih0     = (const float*)d_in[1];
    // d_in[2] = w_hh0      (unused: h0 == 0, T == 1)
    const float* w_ih_rest = (const float*)d_in[3];
    // d_in[4] = w_hh_rest  (unused)
    const float* b_ih      = (const float*)d_in[5];
    const float* b_hh      = (const float*)d_in[6];
    const float* fc_w      = (const float*)d_in[7];
    const float* fc_b      = (const float*)d_in[8];
    float* out = (float*)d_out;

    int B = in_sizes[0] / 64;

    _LSTM_pack<<<(40960 + 544 + 255) / 256, 256>>>(
        w_ih0, w_ih_rest, b_ih, b_hh, fc_w, fc_b);

    cudaFuncSetAttribute(_LSTM_main,
                         cudaFuncAttributeMaxDynamicSharedMemorySize, SMEM_BYTES);
    int npair = (B + NT - 1) / NT;
    int grid = npair < GRID ? npair : GRID;
    _LSTM_main<<<grid, NT, SMEM_BYTES>>>(x, out, B);
}

// round 8
// speedup vs baseline: 1.4399x; 1.4399x over previous
#include <cuda_runtime.h>
#include <cuda_bf16.h>
#include <cstdint>

// ============================================================================
// T=1, h0=c0=0 => w_hh* unused, f-gate unused. Chain of small GEMMs on HMMA
// (mma.sync m16n8k16 bf16; tcgen05 blocked by compute_103 virtual arch).
// bf16x3: A segs [hi,hi,lo] vs W segs [Whi,Wlo,Whi].
// R8: 512 threads / 16 warps (R7 showed throughput ~ warp count), but with a
// register diet so ptxas doesn't spill at the 128-reg cap:
//   - single accumulator buffer (no lag pipeline),
//   - A_hi in regs only; A_lo streamed from SMEM in seg2,
//   - ping-pong h regions (epilogue writes never alias A_lo reads),
//   - fused activation (6 MUFU/h), biases pre-scaled by log2e.
// Persistent: 148 CTAs; warp owns 32 rows, warp-private A smem buffer.
// ============================================================================

#define NT    512
#define GRID  148
#define AP    272
#define WIMG  84096
#define WARP_ABUF (32 * AP)
#define SMEM_BYTES (WIMG + 16 * WARP_ABUF)

#define WB_L0 0
#define WB_L1 24576
#define WB_L2 36864
#define WB_L3 49152
#define WB_L4 61440
#define WB_FC 73728
#define BIAS_OFF 81920

#define LOG2E  1.4426950408889634f
#define LOG2E2 2.8853901617765427f

__device__ __align__(16) unsigned char g_img[WIMG];

// ---------------- fast math ----------------
__device__ __forceinline__ float ex2f(float x) {
    float y; asm("ex2.approx.f32 %0, %1;" : "=f"(y) : "f"(x)); return y;
}
__device__ __forceinline__ float rcpf(float x) {
    float y; asm("rcp.approx.f32 %0, %1;" : "=f"(y) : "f"(x)); return y;
}
__device__ __forceinline__ uint32_t packbf2(float a, float b) {
    __nv_bfloat16 ha = __float2bfloat16_rn(a), hb = __float2bfloat16_rn(b);
    return (uint32_t)__bfloat16_as_ushort(ha) |
           ((uint32_t)__bfloat16_as_ushort(hb) << 16);
}
__device__ __forceinline__ float bflo(float v) {
    return v - __bfloat162float(__float2bfloat16_rn(v));
}

// fused LSTM activation: h = sig(o)*tanh(sig(i)*tanh(g)).
// biases arrive pre-scaled: bik = bI*log2e, bgk = bG*2*log2e, bok = bO*log2e.
__device__ __forceinline__ float act_h(float ci, float cg, float co,
                                       float bik, float bgk, float bok) {
    float A  = ex2f(fmaf(ci, LOG2E,  bik));      // e^i
    float Bv = ex2f(fmaf(cg, LOG2E2, bgk));      // e^{2g}
    float r1 = rcpf((A + 1.f) * (Bv + 1.f));
    float c2k = (A * (Bv - 1.f)) * LOG2E2 * r1;  // 2*log2e * sig(i)tanh(g)
    float Cc = ex2f(fmaf(co, LOG2E,  bok));      // e^o
    float D  = ex2f(c2k);                        // e^{2c}
    return (Cc * (D - 1.f)) * rcpf((Cc + 1.f) * (D + 1.f));
}

// ---------------- mma ----------------
__device__ __forceinline__ void mma_bf16(float c[4],
    const uint32_t a[4], uint32_t b0, uint32_t b1) {
    asm volatile(
        "mma.sync.aligned.m16n8k16.row.col.f32.bf16.bf16.f32 "
        "{%0,%1,%2,%3},{%4,%5,%6,%7},{%8,%9},{%0,%1,%2,%3};"
        : "+f"(c[0]), "+f"(c[1]), "+f"(c[2]), "+f"(c[3])
        : "r"(a[0]), "r"(a[1]), "r"(a[2]), "r"(a[3]), "r"(b0), "r"(b1));
}

// ---------------- weight pack (R4 layout; biases pre-scaled) ----------
__global__ void _LSTM_pack(const float* __restrict__ w_ih0,
                           const float* __restrict__ w_ih_rest,
                           const float* __restrict__ b_ih,
                           const float* __restrict__ b_hh,
                           const float* __restrict__ fc_w,
                           const float* __restrict__ fc_b) {
    int i = blockIdx.x * blockDim.x + threadIdx.x;
    if (i < 40960) {
        int fid = i >> 7, r = i & 127;
        int lane = r >> 2, reg = (r >> 1) & 1, half = r & 1;
        int n = lane >> 2;
        int kel = (lane & 3) * 2 + half + reg * 8;
        int layer, kh, ntn, fl;
        if (fid < 96)       { layer = 0; kh = 4; ntn = 12; fl = fid; }
        else if (fid < 288) { layer = 1 + (fid - 96) / 48; kh = 2; ntn = 12;
                              fl = (fid - 96) % 48; }
        else                { layer = 5; kh = 2; ntn = 8; fl = fid - 288; }
        int kidx = fl / ntn, nt = fl % ntn;
        int is_lo = kidx >= kh;
        int k = (is_lo ? kidx - kh : kidx) * 16 + kel;
        int j = nt * 8 + n;
        float w;
        if (layer == 0)      { int rr = j < 32 ? j : j + 32; w = w_ih0[rr * 64 + k]; }
        else if (layer < 5)  { int rr = j < 32 ? j : j + 32;
                               w = w_ih_rest[(layer - 1) * 4096 + rr * 32 + k]; }
        else                 w = fc_w[j * 32 + k];
        __nv_bfloat16 hi = __float2bfloat16_rn(w);
        __nv_bfloat16 v = is_lo ?
            __float2bfloat16_rn(w - __bfloat162float(hi)) : hi;
        *(__nv_bfloat16*)(g_img + fid * 256 + lane * 8 + reg * 4 + half * 2) = v;
    } else if (i < 40960 + 544) {
        int b = i - 40960; float v;
        if (b < 480) {
            int l = b / 96, j = b % 96;
            int rr = j < 32 ? j : j + 32;
            v = b_ih[l * 128 + rr] + b_hh[l * 128 + rr];
            v *= (j >= 32 && j < 64) ? LOG2E2 : LOG2E;   // g rows: 2*log2e
        } else v = fc_b[b - 480];
        *(float*)(g_img + BIAS_OFF + b * 4) = v;
    }
}

// -------- one 96-col LSTM layer, single accum buffer --------
// A_hi in regs (from in_hi); A_lo LDS'd in seg2 (from in_lo);
// h written to out_off (disjoint from in_lo region).
template<int KH>
__device__ __forceinline__ void layer96(
    const unsigned char* __restrict__ wimg, uint32_t wbase,
    const float* __restrict__ biasK, unsigned char* __restrict__ Abuf,
    int in_hi, int in_lo, int out_off, int lane)
{
    const int g = lane >> 2, q4 = lane & 3;
    uint32_t Ah[2][KH][4];
#pragma unroll
    for (int m = 0; m < 2; m++)
#pragma unroll
        for (int tk = 0; tk < KH; tk++) {
            const unsigned char* ab =
                Abuf + in_hi + (m * 16 + g) * AP + 32 * tk + 4 * q4;
            Ah[m][tk][0] = *(const uint32_t*)ab;
            Ah[m][tk][1] = *(const uint32_t*)(ab + 8 * AP);
            Ah[m][tk][2] = *(const uint32_t*)(ab + 16);
            Ah[m][tk][3] = *(const uint32_t*)(ab + 8 * AP + 16);
        }
    __syncwarp();

    const unsigned char* wp = wimg + wbase + lane * 8;
    const unsigned char* lo0 = Abuf + in_lo + g * AP + 4 * q4;
    const unsigned char* lo1 = lo0 + 16 * AP;

#pragma unroll
    for (int ntj = 0; ntj < 4; ntj++) {
        float Ci[2][4], Cg[2][4], Co[2][4];
#pragma unroll
        for (int m = 0; m < 2; m++)
#pragma unroll
            for (int q = 0; q < 4; q++) {
                Ci[m][q] = 0.f; Cg[m][q] = 0.f; Co[m][q] = 0.f;
            }
#pragma unroll
        for (int t = 0; t < 3 * KH; t++) {
            const int seg = t / KH, tk = t % KH;
            const int kg = (seg == 1) ? KH + tk : tk;
            const uint32_t* bi = (const uint32_t*)(wp + (uint32_t)(kg * 12 + ntj) * 256);
            const uint32_t* bg = (const uint32_t*)(wp + (uint32_t)(kg * 12 + 4 + ntj) * 256);
            const uint32_t* bo = (const uint32_t*)(wp + (uint32_t)(kg * 12 + 8 + ntj) * 256);
            uint32_t i0 = bi[0], i1 = bi[1];
            uint32_t g0 = bg[0], g1 = bg[1];
            uint32_t o0 = bo[0], o1 = bo[1];
#pragma unroll
            for (int m = 0; m < 2; m++) {
                uint32_t Ax[4];
                if (seg == 2) {
                    const unsigned char* ab = (m ? lo1 : lo0) + 32 * tk;
                    Ax[0] = *(const uint32_t*)ab;
                    Ax[1] = *(const uint32_t*)(ab + 8 * AP);
                    Ax[2] = *(const uint32_t*)(ab + 16);
                    Ax[3] = *(const uint32_t*)(ab + 8 * AP + 16);
                } else {
                    Ax[0] = Ah[m][tk][0]; Ax[1] = Ah[m][tk][1];
                    Ax[2] = Ah[m][tk][2]; Ax[3] = Ah[m][tk][3];
                }
                mma_bf16(Ci[m], Ax, i0, i1);
                mma_bf16(Cg[m], Ax, g0, g1);
                mma_bf16(Co[m], Ax, o0, o1);
            }
        }
        const int col = ntj * 8 + q4 * 2;
        const float bi0 = biasK[col],      bi1 = biasK[col + 1];
        const float bg0 = biasK[32 + col], bg1 = biasK[33 + col];
        const float bo0 = biasK[64 + col], bo1 = biasK[65 + col];
#pragma unroll
        for (int m = 0; m < 2; m++) {
            float h0 = act_h(Ci[m][0], Cg[m][0], Co[m][0], bi0, bg0, bo0);
            float h1 = act_h(Ci[m][1], Cg[m][1], Co[m][1], bi1, bg1, bo1);
            float h2 = act_h(Ci[m][2], Cg[m][2], Co[m][2], bi0, bg0, bo0);
            float h3 = act_h(Ci[m][3], Cg[m][3], Co[m][3], bi1, bg1, bo1);
            unsigned char* r0 =
                Abuf + out_off + (m * 16 + g) * AP + 4 * (ntj * 4 + q4);
            unsigned char* r1 = r0 + 8 * AP;
            *(uint32_t*)r0        = packbf2(h0, h1);
            *(uint32_t*)(r0 + 64) = packbf2(bflo(h0), bflo(h1));
            *(uint32_t*)r1        = packbf2(h2, h3);
            *(uint32_t*)(r1 + 64) = packbf2(bflo(h2), bflo(h3));
        }
    }
    __syncwarp();
}

// -------- fc: A hi+lo in regs (KH=2 -> only 32 regs), in-place f32 out -----
__device__ __forceinline__ void fc_stage(
    const unsigned char* __restrict__ wimg,
    const float* __restrict__ fb, unsigned char* __restrict__ Abuf, int lane)
{
    const int g = lane >> 2, q4 = lane & 3;
    uint32_t Ah[2][2][4], Al[2][2][4];
#pragma unroll
    for (int m = 0; m < 2; m++)
#pragma unroll
        for (int tk = 0; tk < 2; tk++) {
            const unsigned char* ab =
                Abuf + (m * 16 + g) * AP + 32 * tk + 4 * q4;
            Ah[m][tk][0] = *(const uint32_t*)ab;
            Ah[m][tk][1] = *(const uint32_t*)(ab + 8 * AP);
            Ah[m][tk][2] = *(const uint32_t*)(ab + 16);
            Ah[m][tk][3] = *(const uint32_t*)(ab + 8 * AP + 16);
            const unsigned char* al = ab + 64;
            Al[m][tk][0] = *(const uint32_t*)al;
            Al[m][tk][1] = *(const uint32_t*)(al + 8 * AP);
            Al[m][tk][2] = *(const uint32_t*)(al + 16);
            Al[m][tk][3] = *(const uint32_t*)(al + 8 * AP + 16);
        }
    __syncwarp();

    const unsigned char* wp = wimg + WB_FC + lane * 8;

#pragma unroll
    for (int ntj = 0; ntj < 8; ntj++) {
        float C2[2][4];
#pragma unroll
        for (int m = 0; m < 2; m++)
#pragma unroll
            for (int q = 0; q < 4; q++) C2[m][q] = 0.f;
#pragma unroll
        for (int t = 0; t < 6; t++) {
            const int seg = t / 2, tk = t % 2;
            const int kg = (seg == 1) ? 2 + tk : tk;
            const uint32_t* bf = (const uint32_t*)
                (wp + (uint32_t)(kg * 8 + ntj) * 256);
            uint32_t b0 = bf[0], b1 = bf[1];
#pragma unroll
            for (int m = 0; m < 2; m++) {
                const uint32_t* A = (seg == 2) ? Al[m][tk] : Ah[m][tk];
                mma_bf16(C2[m], A, b0, b1);
            }
        }
        const int col = ntj * 8 + q4 * 2;
        const float b0 = fb[col], b1 = fb[col + 1];
#pragma unroll
        for (int m = 0; m < 2; m++) {
            float* r0 = (float*)(Abuf + (m * 16 + g) * AP + 4 * col);
            float* r1 = (float*)((unsigned char*)r0 + 8 * AP);
            r0[0] = C2[m][0] + b0; r0[1] = C2[m][1] + b1;
            r1[0] = C2[m][2] + b0; r1[1] = C2[m][3] + b1;
        }
    }
    __syncwarp();
}

// ---------------- main persistent kernel ----------------
__global__ void __launch_bounds__(NT, 1)
_LSTM_main(const float* __restrict__ x, float* __restrict__ out, int B) {
    extern __shared__ unsigned char smem[];
    const int tid = threadIdx.x;
    const int wid = tid >> 5;
    const int lane = tid & 31;

#pragma unroll 4
    for (int p = tid; p < WIMG / 16; p += NT)
        ((uint4*)smem)[p] = ((const uint4*)g_img)[p];
    __syncthreads();

    unsigned char* Abuf = smem + WIMG + wid * WARP_ABUF;
    const float* biasK = (const float*)(smem + BIAS_OFF);
    const float4* x4 = (const float4*)x;
    float4* o4 = (float4*)out;

    const int npair = (B + 511) >> 9;

#pragma unroll 1
    for (int it = blockIdx.x; it < npair; it += GRID) {
        const long long rowbase = (long long)it * 512 + wid * 32;

        // ---- load 32 x-rows, bf16 hi [0,128) / lo [128,256) ----
#pragma unroll
        for (int i = 0; i < 16; i++) {
            int p = lane + i * 32;
            int r = p >> 4, c4 = p & 15;
            long long grow = rowbase + r;
            float4 v = (grow < B) ? x4[grow * 16 + c4]
                                  : make_float4(0.f, 0.f, 0.f, 0.f);
            uint32_t hi0 = packbf2(v.x, v.y), hi1 = packbf2(v.z, v.w);
            uint32_t lo0 = packbf2(bflo(v.x), bflo(v.y));
            uint32_t lo1 = packbf2(bflo(v.z), bflo(v.w));
            unsigned char* dst = Abuf + r * AP + 8 * c4;
            *(uint2*)dst         = make_uint2(hi0, hi1);
            *(uint2*)(dst + 128) = make_uint2(lo0, lo1);
        }
        __syncwarp();

        // ---- 5 LSTM layers (ping-pong h regions) + fc ----
        layer96<4>(smem, WB_L0, biasK,       Abuf,   0, 128,   0, lane);
        layer96<2>(smem, WB_L1, biasK + 96,  Abuf,   0,  64, 128, lane);
        layer96<2>(smem, WB_L2, biasK + 192, Abuf, 128, 192,   0, lane);
        layer96<2>(smem, WB_L3, biasK + 288, Abuf,   0,  64, 128, lane);
        layer96<2>(smem, WB_L4, biasK + 384, Abuf, 128, 192,   0, lane);
        fc_stage(smem, biasK + 480, Abuf, lane);

        // ---- coalesced f32 store ----
#pragma unroll
        for (int i = 0; i < 16; i++) {
            int p = lane + i * 32;
            int r = p >> 4, c4 = p & 15;
            long long grow = rowbase + r;
            if (grow < B)
                o4[grow * 16 + c4] = *(const float4*)(Abuf + r * AP + 16 * c4);
        }
        __syncwarp();
    }
}

// ---------------- launch ----------------
extern "C" void kernel_launch(void* const* d_in, const int* in_sizes, int n_in,
                              void* d_out, int out_size) {
    (void)n_in; (void)out_size;
    const float* x         = (const float*)d_in[0];
    const float* w_ih0     = (const float*)d_in[1];
    // d_in[2] = w_hh0      (unused: h0 == 0, T == 1)
    const float* w_ih_rest = (const float*)d_in[3];
    // d_in[4] = w_hh_rest  (unused)
    const float* b_ih      = (const float*)d_in[5];
    const float* b_hh      = (const float*)d_in[6];
    const float* fc_w      = (const float*)d_in[7];
    const float* fc_b      = (const float*)d_in[8];
    float* out = (float*)d_out;

    int B = in_sizes[0] / 64;

    _LSTM_pack<<<(40960 + 544 + 255) / 256, 256>>>(
        w_ih0, w_ih_rest, b_ih, b_hh, fc_w, fc_b);

    cudaFuncSetAttribute(_LSTM_main,
                         cudaFuncAttributeMaxDynamicSharedMemorySize, SMEM_BYTES);
    int npair = (B + 511) / 512;
    int grid = npair < GRID ? npair : GRID;
    _LSTM_main<<<grid, NT, SMEM_BYTES>>>(x, out, B);
}